// round 14
// baseline (speedup 1.0000x reference)
#include <cuda_runtime.h>
#include <cuda_bf16.h>

#define NBATCH 32
#define NSUP   100
#define NWAY   10
#define NZV    1000
#define NQRY   150

// ---------------- device scratch ----------------
__device__ float g_krn   [NBATCH * NSUP * NSUP];          // sup sup^T (bitwise symmetric)
__device__ float g_compat[NBATCH * NSUP * NQRY];
__device__ float g_Hinv  [NBATCH * NWAY * NSUP * NSUP];   // [bc][j*100+i] (symmetric)
__device__ float g_t     [NBATCH * NWAY * NSUP];
// all NZV-state arrays use i2 = c*100 + ss layout
__device__ float g_z  [NBATCH * NZV];
__device__ float g_s  [NBATCH * NZV];
__device__ float g_lam[NBATCH * NZV];
__device__ float g_gz [NBATCH * NZV];
__device__ float g_rp [NBATCH * NZV];
__device__ float g_rc [NBATCH * NZV];
__device__ float g_r1 [NBATCH * NZV];
__device__ float g_d  [NBATCH * NZV];
__device__ float g_nu [NBATCH * NSUP];
__device__ float g_rp2[NBATCH * NSUP];

// ---------------- gram: kernel (100x100) + compat (100x150) ----------------
__global__ void __launch_bounds__(400) k_gram(const float* __restrict__ sup,
                                              const float* __restrict__ qry) {
    int b  = blockIdx.x;
    int c0 = blockIdx.y * 64;
    __shared__ __align__(16) float As[32 * 100];
    __shared__ __align__(16) float Bs[32 * 64];
    int tid = threadIdx.x;
    int tx = tid & 15;
    int ty = tid >> 4;
    float acc[4][4];
#pragma unroll
    for (int u = 0; u < 4; u++)
#pragma unroll
        for (int v = 0; v < 4; v++) acc[u][v] = 0.f;

    const float* supb = sup + (size_t)b * NSUP * 512;
    const float* qryb = qry + (size_t)b * NQRY * 512;

    for (int kt = 0; kt < 512; kt += 32) {
        __syncthreads();
        for (int e = tid; e < NSUP * 32; e += 400) {
            int r = e >> 5, kk = e & 31;
            As[kk * 100 + r] = supb[r * 512 + kt + kk];
        }
        for (int e = tid; e < 64 * 32; e += 400) {
            int cc = e >> 5, kk = e & 31;
            int col = c0 + cc;
            float v = 0.f;
            if (col < NSUP)      v = supb[col * 512 + kt + kk];
            else if (col < 250)  v = qryb[(col - NSUP) * 512 + kt + kk];
            Bs[kk * 64 + cc] = v;
        }
        __syncthreads();
#pragma unroll
        for (int kk = 0; kk < 32; kk++) {
            float4 a  = *(const float4*)(As + kk * 100 + 4 * ty);
            float4 bb = *(const float4*)(Bs + kk * 64 + 4 * tx);
            acc[0][0] = fmaf(a.x, bb.x, acc[0][0]); acc[0][1] = fmaf(a.x, bb.y, acc[0][1]);
            acc[0][2] = fmaf(a.x, bb.z, acc[0][2]); acc[0][3] = fmaf(a.x, bb.w, acc[0][3]);
            acc[1][0] = fmaf(a.y, bb.x, acc[1][0]); acc[1][1] = fmaf(a.y, bb.y, acc[1][1]);
            acc[1][2] = fmaf(a.y, bb.z, acc[1][2]); acc[1][3] = fmaf(a.y, bb.w, acc[1][3]);
            acc[2][0] = fmaf(a.z, bb.x, acc[2][0]); acc[2][1] = fmaf(a.z, bb.y, acc[2][1]);
            acc[2][2] = fmaf(a.z, bb.z, acc[2][2]); acc[2][3] = fmaf(a.z, bb.w, acc[2][3]);
            acc[3][0] = fmaf(a.w, bb.x, acc[3][0]); acc[3][1] = fmaf(a.w, bb.y, acc[3][1]);
            acc[3][2] = fmaf(a.w, bb.z, acc[3][2]); acc[3][3] = fmaf(a.w, bb.w, acc[3][3]);
        }
    }
#pragma unroll
    for (int u = 0; u < 4; u++) {
        int r = 4 * ty + u;
#pragma unroll
        for (int v = 0; v < 4; v++) {
            int col = c0 + 4 * tx + v;
            if (col < NSUP)
                g_krn[b * NSUP * NSUP + r * NSUP + col] = acc[u][v];
            else if (col < 250)
                g_compat[b * NSUP * NQRY + r * NQRY + (col - NSUP)] = acc[u][v];
        }
    }
}

// ---------------- init (i2 layout) ----------------
__global__ void __launch_bounds__(256) k_init(const int* __restrict__ lab) {
    int b = blockIdx.x, tid = threadIdx.x;
    for (int i = tid; i < NZV; i += 256) {
        int gi = b * NZV + i;
        int ss = i % NSUP, c = i / NSUP;
        float y = (lab[b * NSUP + ss] == c) ? 1.f : 0.f;
        g_z[gi] = 0.f; g_s[gi] = 1.f; g_lam[gi] = 1.f; g_gz[gi] = 0.f;
        float rd = 1.f - y;
        float rp = 1.f - 0.1f * y;
        float rc = 0.9f;
        g_rp[gi] = rp;
        g_rc[gi] = rc;
        g_d [gi] = 1.f;
        g_r1[gi] = -rd + (rc - rp);
    }
    for (int ss = tid; ss < NSUP; ss += 256) {
        g_nu [b * NSUP + ss] = 0.f;
        g_rp2[b * NSUP + ss] = 0.f;
    }
}

// ---------------- one rank-1 symmetric sweep step (R9-identical per-thread) ----------------
__device__ __forceinline__ void sweep_step(float A[28], const float* row,
                                           float* nextrow, int r, int base, int k) {
    float invp = __fdividef(1.0f, row[k]);
    float sr = row[r];
    const float4* rowv = (const float4*)(row + base);
    if (r == k) {
#pragma unroll
        for (int m = 0; m < 7; m++) {
            float4 p = rowv[m];
            int j = base + 4 * m;
            A[4*m+0] = (j+0 == k) ? invp : p.x * invp;
            A[4*m+1] = (j+1 == k) ? invp : p.y * invp;
            A[4*m+2] = (j+2 == k) ? invp : p.z * invp;
            A[4*m+3] = (j+3 == k) ? invp : p.w * invp;
        }
    } else {
        float t = (r < k) ? -sr * invp : sr * invp;
        if (k >= base && k < base + 28) {
#pragma unroll
            for (int m = 0; m < 7; m++) {
                float4 p = rowv[m];
                int j = base + 4 * m;
                float u0 = fmaf(-t, p.x, A[4*m+0]);
                float u1 = fmaf(-t, p.y, A[4*m+1]);
                float u2 = fmaf(-t, p.z, A[4*m+2]);
                float u3 = fmaf(-t, p.w, A[4*m+3]);
                A[4*m+0] = (j+0 == k) ? -t : u0;
                A[4*m+1] = (j+1 == k) ? -t : u1;
                A[4*m+2] = (j+2 == k) ? -t : u2;
                A[4*m+3] = (j+3 == k) ? -t : u3;
            }
        } else {
#pragma unroll
            for (int m = 0; m < 7; m++) {
                float4 p = rowv[m];
                A[4*m+0] = fmaf(-t, p.x, A[4*m+0]);
                A[4*m+1] = fmaf(-t, p.y, A[4*m+1]);
                A[4*m+2] = fmaf(-t, p.z, A[4*m+2]);
                A[4*m+3] = fmaf(-t, p.w, A[4*m+3]);
            }
        }
    }
    if (r == k + 1) {
        float4* dst = (float4*)(nextrow + base);
#pragma unroll
        for (int m = 0; m < 7; m++)
            dst[m] = make_float4(A[4*m], A[4*m+1], A[4*m+2], A[4*m+3]);
    }
}

// ---------------- inversion: 2 classes/block (grid=160, block=800) ----------------
__global__ void __launch_bounds__(800, 1) k_invert2() {
    int t = threadIdx.x;
    int mm = t / 400;                 // matrix within block
    int u = t - mm * 400;
    int bc = blockIdx.x * 2 + mm;
    int b = bc / NWAY, c = bc - b * NWAY;
    int r = u % NSUP, cg = u / NSUP;
    int base = 28 * cg;
    float A[28];
    __shared__ __align__(16) float srow[2][2][112];   // [matrix][buf][col]

    const float* K = g_krn + (size_t)b * NSUP * NSUP;
    float dval = 1.0f + g_d[b * NZV + c * NSUP + r];
    float r1v  = g_r1[b * NZV + c * NSUP + r];
#pragma unroll
    for (int jj = 0; jj < 28; jj++) {
        int j = base + jj;
        float v = 0.f;
        if (j < NSUP) { v = K[j * NSUP + r]; if (j == r) v += dval; }   // K symmetric
        else if (j == NSUP) v = r1v;
        A[jj] = v;
    }
    if (r == 0) {
        float4* dst = (float4*)(srow[mm][0] + base);
#pragma unroll
        for (int q = 0; q < 7; q++)
            dst[q] = make_float4(A[4*q], A[4*q+1], A[4*q+2], A[4*q+3]);
    }
    __syncthreads();

    for (int k = 0; k < NSUP; k++) {
        int buf = k & 1;
        sweep_step(A, srow[mm][buf], srow[mm][buf ^ 1], r, base, k);
        __syncthreads();
    }

    // coalesced transposed store (Hinv symmetric -> identical data)
    float* Ho = g_Hinv + (size_t)bc * (NSUP * NSUP);
#pragma unroll
    for (int jj = 0; jj < 28; jj++) {
        int j = base + jj;
        if (j < NSUP) Ho[j * NSUP + r] = A[jj];
    }
    if (cg == 3) g_t[bc * NSUP + r] = A[16];   // col 100 -> t = Hinv r1
}

// ---------------- Schur: 2 batches/block (grid=16, block=1024) ----------------
__global__ void __launch_bounds__(1024, 1) k_schur2(const int* __restrict__ lab) {
    int t = threadIdx.x;
    int ms = t >> 9;                  // batch half (0/1)
    int u = t & 511;                  // tid within half
    int lane = t & 31;
    int wl = u >> 5;                  // warp index within half (0..15)
    int b = blockIdx.x * 2 + ms;
    int r = u % NSUP, cg = u / NSUP;  // meaningful for u<400
    int base = 28 * cg;
    float A[28];
    __shared__ __align__(16) float srow[2][2][112];
    __shared__ float s_dnu[2][NSUP];
    __shared__ float s_dz[2][NZV];
    __shared__ float red[2][16];
    __shared__ float s_res[2][2];

    const float* Hb = g_Hinv + (size_t)b * NWAY * NSUP * NSUP;

    if (u < 400) {
        // S = sum_c Hinv_c (rows via symmetric/coalesced reads); border col = rhs
#pragma unroll
        for (int jj = 0; jj < 28; jj++) {
            int j = base + jj;
            float v = 0.f;
            if (j < NSUP) {
#pragma unroll
                for (int c = 0; c < NWAY; c++)
                    v += Hb[(size_t)c * (NSUP * NSUP) + j * NSUP + r];
            } else if (j == NSUP) {
                v = g_rp2[b * NSUP + r];
#pragma unroll
                for (int c = 0; c < NWAY; c++)
                    v += g_t[(b * NWAY + c) * NSUP + r];
            }
            A[jj] = v;
        }
        if (r == 0) {
            float4* dst = (float4*)(srow[ms][0] + base);
#pragma unroll
            for (int q = 0; q < 7; q++)
                dst[q] = make_float4(A[4*q], A[4*q+1], A[4*q+2], A[4*q+3]);
        }
    }
    __syncthreads();

    for (int k = 0; k < NSUP; k++) {
        int buf = k & 1;
        if (u < 400)
            sweep_step(A, srow[ms][buf], srow[ms][buf ^ 1], r, base, k);
        __syncthreads();
    }
    if (u < 400 && cg == 3) s_dnu[ms][r] = A[16];   // dnu
    __syncthreads();

    // Phase D: dz (warp per i2 row within each half, coalesced over j)
    for (int ri = wl; ri < NZV; ri += 16) {
        int c = ri / NSUP, ss = ri - c * NSUP;
        const float* Hrow = Hb + (size_t)c * (NSUP * NSUP) + ss * NSUP;
        float acc = 0.f;
#pragma unroll
        for (int q = 0; q < 4; q++) {
            int j = lane + 32 * q;
            if (j < NSUP) acc = fmaf(Hrow[j], s_dnu[ms][j], acc);
        }
#pragma unroll
        for (int off = 16; off; off >>= 1) acc += __shfl_xor_sync(0xffffffffu, acc, off);
        if (lane == 0) s_dz[ms][ri] = g_t[(b * NWAY + c) * NSUP + ss] - acc;
    }
    __syncthreads();

    // Phase E: steps, alpha, state update, residuals (i2 layout)
    const float FINF = __int_as_float(0x7f800000);
    float dzv[2], dsv[2], dlv[2], sv[2], lv[2], zv[2], gzv[2];
    float amin = FINF;
#pragma unroll
    for (int q = 0; q < 2; q++) {
        int i = u + q * 512;
        if (i < NZV) {
            int gi = b * NZV + i;
            float dz = s_dz[ms][i];
            float s0 = g_s[gi], l0 = g_lam[gi];
            float ds = -g_rp[gi] - dz;
            float dl = (-g_rc[gi] - l0 * ds) / s0;
            dzv[q] = dz; dsv[q] = ds; dlv[q] = dl; sv[q] = s0; lv[q] = l0;
            if (ds < 0.f) amin = fminf(amin, -s0 / ds);
            if (dl < 0.f) amin = fminf(amin, -l0 / dl);
        }
    }
#pragma unroll
    for (int off = 16; off; off >>= 1) amin = fminf(amin, __shfl_xor_sync(0xffffffffu, amin, off));
    if (lane == 0) red[ms][wl] = amin;
    __syncthreads();
    if (wl == 0) {
        float v = (lane < 16) ? red[ms][lane] : FINF;
#pragma unroll
        for (int off = 8; off; off >>= 1) v = fminf(v, __shfl_xor_sync(0xffffffffu, v, off));
        if (lane == 0) s_res[ms][0] = fminf(1.0f, 0.99f * v);
    }
    __syncthreads();
    float alpha = s_res[ms][0];

    float muloc = 0.f;
#pragma unroll
    for (int q = 0; q < 2; q++) {
        int i = u + q * 512;
        if (i < NZV) {
            int gi = b * NZV + i;
            int ss = i % NSUP;
            float zn = g_z[gi] + alpha * dzv[q]; g_z[gi] = zn; zv[q] = zn;
            float sn = sv[q] + alpha * dsv[q];   g_s[gi] = sn; sv[q] = sn;
            float ln = lv[q] + alpha * dlv[q];   g_lam[gi] = ln; lv[q] = ln;
            float gdz = g_r1[gi] - s_dnu[ms][ss] - g_d[gi] * dzv[q];   // (G dz)_i exactly
            float gzn = g_gz[gi] + alpha * gdz;  g_gz[gi] = gzn; gzv[q] = gzn;
            muloc += sn * ln;
            s_dz[ms][i] = zn;   // reuse as z_new
        }
    }
#pragma unroll
    for (int off = 16; off; off >>= 1) muloc += __shfl_xor_sync(0xffffffffu, muloc, off);
    if (lane == 0) red[ms][wl] = muloc;
    __syncthreads();
    if (wl == 0) {
        float v = (lane < 16) ? red[ms][lane] : 0.f;
#pragma unroll
        for (int off = 8; off; off >>= 1) v += __shfl_xor_sync(0xffffffffu, v, off);
        if (lane == 0) s_res[ms][1] = v;
    }
    __syncthreads();
    float mu = s_res[ms][1] * (1.0f / (float)NZV);

    // nu update (overwrite s_dnu with nu_new) + rp2
    if (u < NSUP) {
        float nn = g_nu[b * NSUP + u] + alpha * s_dnu[ms][u];
        s_dnu[ms][u] = nn;
        g_nu[b * NSUP + u] = nn;
        float acc = 0.f;
#pragma unroll
        for (int c = 0; c < NWAY; c++) acc += s_dz[ms][c * NSUP + u];
        g_rp2[b * NSUP + u] = acc;
    }
    __syncthreads();

    // next-iteration residuals (elementwise; no matvec)
#pragma unroll
    for (int q = 0; q < 2; q++) {
        int i = u + q * 512;
        if (i < NZV) {
            int gi = b * NZV + i;
            int ss = i % NSUP, c = i / NSUP;
            float y = (lab[b * NSUP + ss] == c) ? 1.f : 0.f;
            float rd = gzv[q] - y + lv[q] + s_dnu[ms][ss];
            float rp = zv[q] + sv[q] - 0.1f * y;
            float rc = lv[q] * sv[q] - 0.1f * mu;
            float invs = 1.0f / sv[q];
            g_rp[gi] = rp;
            g_rc[gi] = rc;
            g_d [gi] = lv[q] * invs;
            g_r1[gi] = -rd + (rc - lv[q] * rp) * invs;
        }
    }
}

// ---------------- logits epilogue ----------------
__global__ void __launch_bounds__(256) k_logits(float* __restrict__ out) {
    int b = blockIdx.x, tid = threadIdx.x;
    __shared__ float sh_z[NZV];
    for (int i = tid; i < NZV; i += 256) sh_z[i] = g_z[b * NZV + i];
    __syncthreads();
    const float* cb = &g_compat[b * NSUP * NQRY];
    for (int o = tid; o < NQRY * NWAY; o += 256) {
        int q = o / NWAY, n = o - q * NWAY;
        float acc = 0.f;
        for (int s = 0; s < NSUP; s++)
            acc = fmaf(cb[s * NQRY + q], sh_z[n * NSUP + s], acc);
        out[b * NQRY * NWAY + o] = acc;
    }
}

// ---------------- launcher ----------------
extern "C" void kernel_launch(void* const* d_in, const int* in_sizes, int n_in,
                              void* d_out, int out_size) {
    const float* sup = (const float*)d_in[0];
    const int*   lab = (const int*)  d_in[1];
    const float* qry = (const float*)d_in[2];
    float* out = (float*)d_out;

    k_gram<<<dim3(NBATCH, 4), 400>>>(sup, qry);
    k_init<<<NBATCH, 256>>>(lab);
    for (int it = 0; it < 15; ++it) {
        k_invert2<<<NBATCH * NWAY / 2, 800>>>();
        k_schur2<<<NBATCH / 2, 1024>>>(lab);
    }
    k_logits<<<NBATCH, 256>>>(out);
}